// round 15
// baseline (speedup 1.0000x reference)
#include <cuda_runtime.h>
#include <math.h>
#include <stdint.h>

#define B_  8192
#define D_  256
#define M_  10
#define H_  4
#define DK_ 64

// ---------------- scratch (device globals; no allocation allowed) ----------
__device__ float g_z    [B_*D_];
__device__ float g_xp   [B_*3*D_];
__device__ float g_hp   [B_*3*D_];
__device__ float g_gru  [B_*D_];
__device__ float g_k    [B_*M_*D_];
__device__ float g_v    [B_*M_*D_];
__device__ float g_ctxh [B_*D_];
__device__ float g_ctx  [B_*D_];
__device__ float g_ctxp [B_*D_];
__device__ float g_part1[B_*D_];

__device__ __forceinline__ float sigf(float x) { return 1.0f / (1.0f + expf(-x)); }

__device__ __forceinline__ void mma_tf32(float acc[4], const uint32_t a[4],
                                         uint32_t b0, uint32_t b1) {
    asm volatile(
        "mma.sync.aligned.m16n8k8.row.col.f32.tf32.tf32.f32 "
        "{%0,%1,%2,%3}, {%4,%5,%6,%7}, {%8,%9}, {%0,%1,%2,%3};"
        : "+f"(acc[0]), "+f"(acc[1]), "+f"(acc[2]), "+f"(acc[3])
        : "r"(a[0]), "r"(a[1]), "r"(a[2]), "r"(a[3]), "r"(b0), "r"(b1));
}

__device__ __forceinline__ void cp16(uint32_t dst, const void* src) {
    asm volatile("cp.async.cg.shared.global [%0], [%1], 16;" :: "r"(dst), "l"(src));
}
__device__ __forceinline__ void cp_commit() {
    asm volatile("cp.async.commit_group;" ::: "memory");
}
template<int N>
__device__ __forceinline__ void cp_wait() {
    asm volatile("cp.async.wait_group %0;" :: "n"(N) : "memory");
}

// ---- smem geometry (words) ----
#define AS_STRIDE 36
#define ABUF_W    (128 * AS_STRIDE)          // 4608
#define BS_STRIDE 72
#define BBUF_W    (32 * BS_STRIDE)           // 2304
#define STAGE_W   (ABUF_W + BBUF_W)
#define SMEM_BYTES  (2 * STAGE_W * 4)        // 55296
#define SMEM2_BYTES ((2 * ABUF_W + 4 * BBUF_W) * 4)  // 73728 (dual-B)
// row-kernel (BM=64, BN=256)
#define R_ABUF    (64 * 36)                  // 2304
#define R_BSTRIDE 264
#define R_BBUF    (32 * R_BSTRIDE)           // 8448
#define R_STAGE   (R_ABUF + R_BBUF)          // 10752
#define RSMEM_BYTES (2 * R_STAGE * 4)        // 86016

// ---------------- tf32 GEMM core (device, single B) -------------------------
// EPI: 0=identity, 1=tanh, 3=fused attention epilogue.
template<int EPI, bool DUAL>
__device__ __forceinline__
void gemm_core(const float* __restrict__ A, const float* __restrict__ A2,
               const float* __restrict__ W, const float* __restrict__ bias,
               float* __restrict__ C, int N, int K, int ldc)
{
    extern __shared__ uint32_t sm[];
    const uint32_t sbase = (uint32_t)__cvta_generic_to_shared(sm);

    const int bm   = blockIdx.y * 128;
    const int bn   = blockIdx.x * 64;
    const int tid  = threadIdx.x;
    const int lane = tid & 31;
    const int wid  = tid >> 5;
    const int wm   = (wid & 3) * 32;
    const int wn   = (wid >> 2) * 32;
    const int g    = lane >> 2;
    const int q    = lane & 3;

    const int mi = lane >> 3, rr = lane & 7;
    const uint32_t a_off0 = ((wm + (mi & 1) * 8 + rr) * AS_STRIDE + (mi >> 1) * 4) * 4;
    const uint32_t a_off1 = a_off0 + 16 * AS_STRIDE * 4;
    const uint32_t b_off  = (q * BS_STRIDE + wn + g) * 4;

    float acc[2][4][4];
    #pragma unroll
    for (int t = 0; t < 2; t++)
        #pragma unroll
        for (int j = 0; j < 4; j++)
            #pragma unroll
            for (int e = 0; e < 4; e++) acc[t][j][e] = 0.0f;

    auto cp_tile = [&](int k0, int stage) {
        uint32_t abase = sbase + stage * (STAGE_W * 4);
        uint32_t bbase = abase + ABUF_W * 4;
        #pragma unroll
        for (int i = 0; i < 4; i++) {
            int idx = tid + i * 256;
            int row = idx >> 3, c4 = (idx & 7) * 4;
            int gk  = k0 + c4;
            const float* src;
            if (DUAL) {
                src = (gk < 256) ? &A [(size_t)(bm + row) * 256 + gk]
                                 : &A2[(size_t)(bm + row) * 256 + gk - 256];
            } else {
                src = &A[(size_t)(bm + row) * K + gk];
            }
            cp16(abase + (row * AS_STRIDE + c4) * 4, src);
        }
        #pragma unroll
        for (int i = 0; i < 2; i++) {
            int idx = tid + i * 256;
            int kk = idx >> 4, n0 = (idx & 15) * 4;
            cp16(bbase + (kk * BS_STRIDE + n0) * 4, &W[(size_t)(k0 + kk) * N + bn + n0]);
        }
    };

    auto load_frag = [&](uint32_t asb, uint32_t bsb, int kb,
                         uint32_t a0[4], uint32_t a1[4], uint32_t b0[4], uint32_t b1[4]) {
        asm volatile("ldmatrix.sync.aligned.m8n8.x4.shared.b16 {%0,%1,%2,%3}, [%4];"
            : "=r"(a0[0]), "=r"(a0[1]), "=r"(a0[2]), "=r"(a0[3]) : "r"(asb + a_off0 + kb * 32));
        asm volatile("ldmatrix.sync.aligned.m8n8.x4.shared.b16 {%0,%1,%2,%3}, [%4];"
            : "=r"(a1[0]), "=r"(a1[1]), "=r"(a1[2]), "=r"(a1[3]) : "r"(asb + a_off1 + kb * 32));
        uint32_t bb = bsb + b_off + kb * (8 * BS_STRIDE * 4);
        #pragma unroll
        for (int j = 0; j < 4; j++) {
            asm volatile("ld.shared.b32 %0, [%1];" : "=r"(b0[j]) : "r"(bb + j * 32));
            asm volatile("ld.shared.b32 %0, [%1];" : "=r"(b1[j]) : "r"(bb + j * 32 + 4 * BS_STRIDE * 4));
        }
    };

    auto compute = [&](int stage) {
        const uint32_t asb = sbase + stage * (STAGE_W * 4);
        const uint32_t bsb = asb + ABUF_W * 4;
        uint32_t a0[2][4], a1[2][4], b0[2][4], b1[2][4];
        load_frag(asb, bsb, 0, a0[0], a1[0], b0[0], b1[0]);
        #pragma unroll
        for (int kb = 0; kb < 4; kb++) {
            int cur = kb & 1, nxt = cur ^ 1;
            if (kb < 3) load_frag(asb, bsb, kb + 1, a0[nxt], a1[nxt], b0[nxt], b1[nxt]);
            #pragma unroll
            for (int j = 0; j < 4; j++) {
                mma_tf32(acc[0][j], a0[cur], b0[cur][j], b1[cur][j]);
                mma_tf32(acc[1][j], a1[cur], b0[cur][j], b1[cur][j]);
            }
        }
    };

    const int NIT = K >> 5;
    cp_tile(0, 0);
    cp_commit();
    for (int it = 0; it < NIT; it++) {
        cp_wait<0>();
        __syncthreads();
        if (it + 1 < NIT) {
            cp_tile((it + 1) * 32, (it + 1) & 1);
            cp_commit();
        }
        compute(it & 1);
    }

    if (EPI == 3) {
        float* qs = (float*)sm;            // 128 x 68 staging
        __syncthreads();
        #pragma unroll
        for (int t = 0; t < 2; t++) {
            #pragma unroll
            for (int j = 0; j < 4; j++) {
                int colL = wn + j * 8 + 2 * q;
                float b0v = bias[bn + colL], b1v = bias[bn + colL + 1];
                #pragma unroll
                for (int h2 = 0; h2 < 2; h2++) {
                    int rowL = wm + t * 16 + g + h2 * 8;
                    qs[rowL * 68 + colL]     = acc[t][j][2 * h2]     + b0v;
                    qs[rowL * 68 + colL + 1] = acc[t][j][2 * h2 + 1] + b1v;
                }
            }
        }
        __syncthreads();
        const int head = blockIdx.x;       // bn = 64*head
        for (int r2 = 0; r2 < 16; r2++) {
            int row = wid * 16 + r2;
            size_t b = bm + row;
            float2 qv = *(float2*)&qs[row * 68 + 2 * lane];
            float sc[M_];
            #pragma unroll
            for (int m = 0; m < M_; m++) {
                const float* kp = g_k + (b * M_ + m) * D_ + head * DK_;
                float p = qv.x * kp[2 * lane] + qv.y * kp[2 * lane + 1];
                #pragma unroll
                for (int o = 16; o > 0; o >>= 1) p += __shfl_xor_sync(0xffffffffu, p, o);
                sc[m] = p * 0.125f;
            }
            float mx = sc[0];
            #pragma unroll
            for (int m = 1; m < M_; m++) mx = fmaxf(mx, sc[m]);
            float sum = 0.0f;
            #pragma unroll
            for (int m = 0; m < M_; m++) { sc[m] = expf(sc[m] - mx); sum += sc[m]; }
            float inv = 1.0f / sum;
            float c0 = 0.0f, c1 = 0.0f;
            #pragma unroll
            for (int m = 0; m < M_; m++) {
                const float* vp = g_v + (b * M_ + m) * D_ + head * DK_;
                float a = sc[m] * inv;
                c0 += a * vp[2 * lane];
                c1 += a * vp[2 * lane + 1];
            }
            *(float2*)&C[b * ldc + bn + 2 * lane] = make_float2(c0, c1);
        }
        return;
    }

    #pragma unroll
    for (int t = 0; t < 2; t++) {
        #pragma unroll
        for (int j = 0; j < 4; j++) {
            int col = bn + wn + j * 8 + 2 * q;
            float b0 = bias[col], b1 = bias[col + 1];
            #pragma unroll
            for (int h = 0; h < 2; h++) {
                int row = bm + wm + t * 16 + g + h * 8;
                float v0 = acc[t][j][2 * h]     + b0;
                float v1 = acc[t][j][2 * h + 1] + b1;
                if (EPI == 1) { v0 = tanhf(v0); v1 = tanhf(v1); }
                *(float2*)&C[(size_t)row * ldc + col] = make_float2(v0, v1);
            }
        }
    }
}

template<int EPI, bool DUAL>
__global__ __launch_bounds__(256, 4)
void gemm_single(const float* __restrict__ A, const float* __restrict__ A2,
                 const float* __restrict__ W, const float* __restrict__ bias,
                 float* __restrict__ C, int N, int K, int ldc)
{
    gemm_core<EPI, DUAL>(A, A2, W, bias, C, N, K, ldc);
}

// q-attention GEMM (z=0) + gate-part1 GEMM (z=1), both consume gru
__global__ __launch_bounds__(256, 4)
void qpair_kernel(const float* __restrict__ gru,
                  const float* __restrict__ Wq, const float* __restrict__ bq,
                  float* __restrict__ ctxh,
                  const float* __restrict__ Wg1, const float* __restrict__ bg,
                  float* __restrict__ part1)
{
    if (blockIdx.z == 0)
        gemm_core<3, false>(gru, nullptr, Wq, bq, ctxh, 256, 256, 256);
    else
        gemm_core<0, false>(gru, nullptr, Wg1, bg, part1, 256, 256, 256);
}

// z-batched wrapper (independent slices)
struct Slice {
    const float* A; const float* W; const float* bias; float* C;
    int N; int K; int ldc; int gx;
};
struct Batch3 { Slice s[3]; };

__global__ __launch_bounds__(256, 4)
void gemm_batched(Batch3 p)
{
    Slice sl = p.s[blockIdx.z];
    if ((int)blockIdx.x >= sl.gx) return;
    gemm_core<0, false>(sl.A, nullptr, sl.W, sl.bias, sl.C, sl.N, sl.K, sl.ldc);
}

// ---------------- dual-B shared-A GEMM: C0 = A@W0+b0, C1 = A@W1+b1 ----------
__global__ __launch_bounds__(256, 2)
void gemm_dualB(const float* __restrict__ A,
                const float* __restrict__ W0, const float* __restrict__ bias0,
                float* __restrict__ C0, int ldc0,
                const float* __restrict__ W1, const float* __restrict__ bias1,
                float* __restrict__ C1, int ldc1,
                int N, int K)
{
    extern __shared__ uint32_t sm[];
    const uint32_t sbase = (uint32_t)__cvta_generic_to_shared(sm);

    const int bm   = blockIdx.y * 128;
    const int bn   = blockIdx.x * 64;
    const int tid  = threadIdx.x;
    const int lane = tid & 31;
    const int wid  = tid >> 5;
    const int wm   = (wid & 3) * 32;
    const int wn   = (wid >> 2) * 32;
    const int g    = lane >> 2;
    const int q    = lane & 3;

    const int mi = lane >> 3, rr = lane & 7;
    const uint32_t a_off0 = ((wm + (mi & 1) * 8 + rr) * AS_STRIDE + (mi >> 1) * 4) * 4;
    const uint32_t a_off1 = a_off0 + 16 * AS_STRIDE * 4;
    const uint32_t b_off  = (q * BS_STRIDE + wn + g) * 4;

    float acc[2][2][4][4];
    #pragma unroll
    for (int p = 0; p < 2; p++)
        #pragma unroll
        for (int t = 0; t < 2; t++)
            #pragma unroll
            for (int j = 0; j < 4; j++)
                #pragma unroll
                for (int e = 0; e < 4; e++) acc[p][t][j][e] = 0.0f;

    auto cp_tile = [&](int k0, int stage) {
        uint32_t abase  = sbase + stage * (ABUF_W * 4);
        uint32_t bbase0 = sbase + (2 * ABUF_W + (2 * stage + 0) * BBUF_W) * 4;
        uint32_t bbase1 = sbase + (2 * ABUF_W + (2 * stage + 1) * BBUF_W) * 4;
        #pragma unroll
        for (int i = 0; i < 4; i++) {
            int idx = tid + i * 256;
            int row = idx >> 3, c4 = (idx & 7) * 4;
            cp16(abase + (row * AS_STRIDE + c4) * 4, &A[(size_t)(bm + row) * K + k0 + c4]);
        }
        #pragma unroll
        for (int i = 0; i < 2; i++) {
            int idx = tid + i * 256;
            int kk = idx >> 4, n0 = (idx & 15) * 4;
            cp16(bbase0 + (kk * BS_STRIDE + n0) * 4, &W0[(size_t)(k0 + kk) * N + bn + n0]);
            cp16(bbase1 + (kk * BS_STRIDE + n0) * 4, &W1[(size_t)(k0 + kk) * N + bn + n0]);
        }
    };

    auto compute = [&](int stage) {
        const uint32_t asb = sbase + stage * (ABUF_W * 4);
        #pragma unroll
        for (int kb = 0; kb < 4; kb++) {
            uint32_t a0[4], a1[4];
            asm volatile("ldmatrix.sync.aligned.m8n8.x4.shared.b16 {%0,%1,%2,%3}, [%4];"
                : "=r"(a0[0]), "=r"(a0[1]), "=r"(a0[2]), "=r"(a0[3])
                : "r"(asb + a_off0 + kb * 32));
            asm volatile("ldmatrix.sync.aligned.m8n8.x4.shared.b16 {%0,%1,%2,%3}, [%4];"
                : "=r"(a1[0]), "=r"(a1[1]), "=r"(a1[2]), "=r"(a1[3])
                : "r"(asb + a_off1 + kb * 32));
            #pragma unroll
            for (int p = 0; p < 2; p++) {
                uint32_t bsb = sbase + (2 * ABUF_W + (2 * stage + p) * BBUF_W) * 4;
                uint32_t bb  = bsb + b_off + kb * (8 * BS_STRIDE * 4);
                uint32_t b0[4], b1[4];
                #pragma unroll
                for (int j = 0; j < 4; j++) {
                    asm volatile("ld.shared.b32 %0, [%1];" : "=r"(b0[j]) : "r"(bb + j * 32));
                    asm volatile("ld.shared.b32 %0, [%1];" : "=r"(b1[j]) : "r"(bb + j * 32 + 4 * BS_STRIDE * 4));
                }
                #pragma unroll
                for (int j = 0; j < 4; j++) {
                    mma_tf32(acc[p][0][j], a0, b0[j], b1[j]);
                    mma_tf32(acc[p][1][j], a1, b0[j], b1[j]);
                }
            }
        }
    };

    const int NIT = K >> 5;
    cp_tile(0, 0);
    cp_commit();
    for (int it = 0; it < NIT; it++) {
        cp_wait<0>();
        __syncthreads();
        if (it + 1 < NIT) {
            cp_tile((it + 1) * 32, (it + 1) & 1);
            cp_commit();
        }
        compute(it & 1);
    }

    #pragma unroll
    for (int p = 0; p < 2; p++) {
        const float* bias = p ? bias1 : bias0;
        float*       C    = p ? C1    : C0;
        int          ldc  = p ? ldc1  : ldc0;
        #pragma unroll
        for (int t = 0; t < 2; t++) {
            #pragma unroll
            for (int j = 0; j < 4; j++) {
                int col = bn + wn + j * 8 + 2 * q;
                float b0 = bias[col], b1 = bias[col + 1];
                #pragma unroll
                for (int h = 0; h < 2; h++) {
                    int row = bm + wm + t * 16 + g + h * 8;
                    *(float2*)&C[(size_t)row * ldc + col] =
                        make_float2(acc[p][t][j][2 * h] + b0, acc[p][t][j][2 * h + 1] + b1);
                }
            }
        }
    }
}

// ---------------- LayerNorm helper (warp holds one row via x8) --------------
__device__ __forceinline__ void ln_row(const float* x8, int lane,
                                       const float* __restrict__ gm,
                                       const float* __restrict__ bt,
                                       float* __restrict__ yrow)
{
    float s = 0.0f, ss = 0.0f;
    #pragma unroll
    for (int i = 0; i < 8; i++) { s += x8[i]; ss += x8[i] * x8[i]; }
    #pragma unroll
    for (int o = 16; o > 0; o >>= 1) {
        s  += __shfl_xor_sync(0xffffffffu, s,  o);
        ss += __shfl_xor_sync(0xffffffffu, ss, o);
    }
    float mu  = s * (1.0f / 256.0f);
    float var = ss * (1.0f / 256.0f) - mu * mu;
    float inv = rsqrtf(var + 1e-3f);
    float out[8];
    #pragma unroll
    for (int i = 0; i < 8; i++) {
        int d = lane * 8 + i;
        out[i] = (x8[i] - mu) * inv * gm[d] + bt[d];
    }
    *(float4*)(yrow + lane * 8)     = make_float4(out[0], out[1], out[2], out[3]);
    *(float4*)(yrow + lane * 8 + 4) = make_float4(out[4], out[5], out[6], out[7]);
}

// ---------------- row GEMM: BM=64, BN=256 (full row) + fused LN epilogue ----
// MODE 0: C = LN(A@W + bias)                       (Wo -> ctx, gamma/beta attn)
// MODE 1: alpha = sig(part1 + A@W + bias);
//         C = LN((1-alpha)*gru + alpha*ctxp)       (gate2+blend -> h_corr)
// 8 warps: wm = (wid&1)*32, wn = (wid>>1)*64. Warp tile 32x64 (j=0..7). K=256.
template<int MODE>
__global__ __launch_bounds__(256, 2)
void gemm_row(const float* __restrict__ A, const float* __restrict__ W,
              const float* __restrict__ bias,
              const float* __restrict__ gm, const float* __restrict__ bt,
              const float* __restrict__ part1, const float* __restrict__ gru,
              const float* __restrict__ ctxp,
              float* __restrict__ C)
{
    extern __shared__ uint32_t sm[];
    const uint32_t sbase = (uint32_t)__cvta_generic_to_shared(sm);

    const int bm   = blockIdx.x * 64;
    const int tid  = threadIdx.x;
    const int lane = tid & 31;
    const int wid  = tid >> 5;
    const int wm   = (wid & 1) * 32;
    const int wn   = (wid >> 1) * 64;
    const int g    = lane >> 2;
    const int q    = lane & 3;

    const int mi = lane >> 3, rr = lane & 7;
    const uint32_t a_off0 = ((wm + (mi & 1) * 8 + rr) * 36 + (mi >> 1) * 4) * 4;
    const uint32_t a_off1 = a_off0 + 16 * 36 * 4;
    const uint32_t b_off  = (q * R_BSTRIDE + wn + g) * 4;

    float acc[2][8][4];
    #pragma unroll
    for (int t = 0; t < 2; t++)
        #pragma unroll
        for (int j = 0; j < 8; j++)
            #pragma unroll
            for (int e = 0; e < 4; e++) acc[t][j][e] = 0.0f;

    auto cp_tile = [&](int k0, int stage) {
        uint32_t abase = sbase + stage * (R_STAGE * 4);
        uint32_t bbase = abase + R_ABUF * 4;
        #pragma unroll
        for (int i = 0; i < 2; i++) {
            int idx = tid + i * 256;
            int row = idx >> 3, c4 = (idx & 7) * 4;
            cp16(abase + (row * 36 + c4) * 4, &A[(size_t)(bm + row) * 256 + k0 + c4]);
        }
        #pragma unroll
        for (int i = 0; i < 8; i++) {
            int idx = tid + i * 256;
            int kk = idx >> 6, n0 = (idx & 63) * 4;
            cp16(bbase + (kk * R_BSTRIDE + n0) * 4, &W[(size_t)(k0 + kk) * 256 + n0]);
        }
    };

    auto compute = [&](int stage) {
        const uint32_t asb = sbase + stage * (R_STAGE * 4);
        const uint32_t bsb = asb + R_ABUF * 4;
        #pragma unroll
        for (int kb = 0; kb < 4; kb++) {
            uint32_t a0[4], a1[4];
            asm volatile("ldmatrix.sync.aligned.m8n8.x4.shared.b16 {%0,%1,%2,%3}, [%4];"
                : "=r"(a0[0]), "=r"(a0[1]), "=r"(a0[2]), "=r"(a0[3])
                : "r"(asb + a_off0 + kb * 32));
            asm volatile("ldmatrix.sync.aligned.m8n8.x4.shared.b16 {%0,%1,%2,%3}, [%4];"
                : "=r"(a1[0]), "=r"(a1[1]), "=r"(a1[2]), "=r"(a1[3])
                : "r"(asb + a_off1 + kb * 32));
            uint32_t bb = bsb + b_off + kb * (8 * R_BSTRIDE * 4);
            #pragma unroll
            for (int j = 0; j < 8; j++) {
                uint32_t b0, b1;
                asm volatile("ld.shared.b32 %0, [%1];" : "=r"(b0) : "r"(bb + j * 32));
                asm volatile("ld.shared.b32 %0, [%1];" : "=r"(b1) : "r"(bb + j * 32 + 4 * R_BSTRIDE * 4));
                mma_tf32(acc[0][j], a0, b0, b1);
                mma_tf32(acc[1][j], a1, b0, b1);
            }
        }
    };

    const int NIT = 8;   // K = 256
    cp_tile(0, 0);
    cp_commit();
    for (int it = 0; it < NIT; it++) {
        cp_wait<0>();
        __syncthreads();
        if (it + 1 < NIT) {
            cp_tile((it + 1) * 32, (it + 1) & 1);
            cp_commit();
        }
        compute(it & 1);
    }

    // ---- epilogue: stage full rows, fused LN ----
    float* st = (float*)sm;   // [64][R_BSTRIDE] floats
    __syncthreads();
    #pragma unroll
    for (int t = 0; t < 2; t++) {
        #pragma unroll
        for (int j = 0; j < 8; j++) {
            int col = wn + j * 8 + 2 * q;
            float b0 = bias[col], b1 = bias[col + 1];
            #pragma unroll
            for (int h = 0; h < 2; h++) {
                int row = wm + t * 16 + g + h * 8;
                float v0 = acc[t][j][2 * h]     + b0;
                float v1 = acc[t][j][2 * h + 1] + b1;
                if (MODE == 1) {
                    size_t gi = (size_t)(bm + row) * 256 + col;
                    float a0v = sigf(part1[gi]     + v0);
                    float a1v = sigf(part1[gi + 1] + v1);
                    v0 = (1.0f - a0v) * gru[gi]     + a0v * ctxp[gi];
                    v1 = (1.0f - a1v) * gru[gi + 1] + a1v * ctxp[gi + 1];
                }
                st[row * R_BSTRIDE + col]     = v0;
                st[row * R_BSTRIDE + col + 1] = v1;
            }
        }
    }
    __syncthreads();
    // LN: warp wid handles rows wid*8 .. wid*8+7
    for (int r2 = 0; r2 < 8; r2++) {
        int row = wid * 8 + r2;
        float x8[8];
        float4 v0 = *(float4*)&st[row * R_BSTRIDE + lane * 8];
        float4 v1 = *(float4*)&st[row * R_BSTRIDE + lane * 8 + 4];
        x8[0]=v0.x; x8[1]=v0.y; x8[2]=v0.z; x8[3]=v0.w;
        x8[4]=v1.x; x8[5]=v1.y; x8[6]=v1.z; x8[7]=v1.w;
        ln_row(x8, lane, gm, bt, C + (size_t)(bm + row) * 256);
    }
}

// ---------------- GRU elementwise, float4 vectorized ------------------------
__global__ void gru_kernel(const float* __restrict__ h_prev)
{
    int idx = blockIdx.x * blockDim.x + threadIdx.x;
    if (idx >= B_ * 64) return;
    int b = idx >> 6, d4 = (idx & 63) * 4;
    const float* xp = g_xp + (size_t)b * 768;
    const float* hp = g_hp + (size_t)b * 768;
    float4 xz = *(const float4*)(xp + d4);
    float4 xr = *(const float4*)(xp + 256 + d4);
    float4 xh = *(const float4*)(xp + 512 + d4);
    float4 hz = *(const float4*)(hp + d4);
    float4 hr = *(const float4*)(hp + 256 + d4);
    float4 hh = *(const float4*)(hp + 512 + d4);
    float4 h  = *(const float4*)(h_prev + (size_t)b * 256 + d4);
    float4 o;
    { float z = sigf(xz.x + hz.x), r = sigf(xr.x + hr.x);
      float hc = tanhf(xh.x + r * hh.x); o.x = z * h.x + (1.0f - z) * hc; }
    { float z = sigf(xz.y + hz.y), r = sigf(xr.y + hr.y);
      float hc = tanhf(xh.y + r * hh.y); o.y = z * h.y + (1.0f - z) * hc; }
    { float z = sigf(xz.z + hz.z), r = sigf(xr.z + hr.z);
      float hc = tanhf(xh.z + r * hh.z); o.z = z * h.z + (1.0f - z) * hc; }
    { float z = sigf(xz.w + hz.w), r = sigf(xr.w + hr.w);
      float hc = tanhf(xh.w + r * hh.w); o.w = z * h.w + (1.0f - z) * hc; }
    *(float4*)(g_gru + (size_t)b * 256 + d4) = o;
}

// ---------------- memory shift ---------------------------------------------
__global__ void memshift_kernel(const float* __restrict__ memflat,
                                float* __restrict__ outmem)
{
    const int per = (M_ - 1) * D_ / 4;
    int idx = blockIdx.x * blockDim.x + threadIdx.x;
    if (idx >= B_ * per) return;
    int b = idx / per, j = idx - b * per;
    const float4* src = (const float4*)(memflat + (size_t)b * (M_ * D_) + D_);
    float4*       dst = (float4*)(outmem + (size_t)b * (M_ * D_));
    dst[j] = src[j];
}

// ---------------- host ------------------------------------------------------
extern "C" void kernel_launch(void* const* d_in, const int* in_sizes, int n_in,
                              void* d_out, int out_size)
{
    const float* inputs    = (const float*)d_in[0];
    const float* h_prev    = (const float*)d_in[1];
    const float* memflat   = (const float*)d_in[2];
    const float* W_in      = (const float*)d_in[3];
    const float* b_in      = (const float*)d_in[4];
    const float* gru_k     = (const float*)d_in[5];
    const float* gru_rk    = (const float*)d_in[6];
    const float* gru_b     = (const float*)d_in[7];
    const float* Wq        = (const float*)d_in[8];
    const float* bq        = (const float*)d_in[9];
    const float* Wk        = (const float*)d_in[10];
    const float* bk        = (const float*)d_in[11];
    const float* Wv        = (const float*)d_in[12];
    const float* bv        = (const float*)d_in[13];
    const float* Wo        = (const float*)d_in[14];
    const float* bo        = (const float*)d_in[15];
    const float* g_attn    = (const float*)d_in[16];
    const float* beta_attn = (const float*)d_in[17];
    const float* g_out     = (const float*)d_in[18];
    const float* beta_out  = (const float*)d_in[19];
    const float* W_ctx     = (const float*)d_in[20];
    const float* b_ctx     = (const float*)d_in[21];
    const float* W_gate    = (const float*)d_in[22];
    const float* b_gate    = (const float*)d_in[23];
    const float* W_mem     = (const float*)d_in[24];
    const float* b_mem     = (const float*)d_in[25];
    float* out = (float*)d_out;

    float *zP, *xpP, *hpP, *gruP, *kP, *vP, *ctxhP, *ctxP, *ctxpP, *p1P;
    cudaGetSymbolAddress((void**)&zP,    g_z);
    cudaGetSymbolAddress((void**)&xpP,   g_xp);
    cudaGetSymbolAddress((void**)&hpP,   g_hp);
    cudaGetSymbolAddress((void**)&gruP,  g_gru);
    cudaGetSymbolAddress((void**)&kP,    g_k);
    cudaGetSymbolAddress((void**)&vP,    g_v);
    cudaGetSymbolAddress((void**)&ctxhP, g_ctxh);
    cudaGetSymbolAddress((void**)&ctxP,  g_ctx);
    cudaGetSymbolAddress((void**)&ctxpP, g_ctxp);
    cudaGetSymbolAddress((void**)&p1P,   g_part1);

    cudaFuncSetAttribute(gemm_single<0,false>, cudaFuncAttributeMaxDynamicSharedMemorySize, SMEM_BYTES);
    cudaFuncSetAttribute(gemm_single<1,false>, cudaFuncAttributeMaxDynamicSharedMemorySize, SMEM_BYTES);
    cudaFuncSetAttribute(qpair_kernel,         cudaFuncAttributeMaxDynamicSharedMemorySize, SMEM_BYTES);
    cudaFuncSetAttribute(gemm_batched,         cudaFuncAttributeMaxDynamicSharedMemorySize, SMEM_BYTES);
    cudaFuncSetAttribute(gemm_dualB,           cudaFuncAttributeMaxDynamicSharedMemorySize, SMEM2_BYTES);
    cudaFuncSetAttribute(gemm_row<0>,          cudaFuncAttributeMaxDynamicSharedMemorySize, RSMEM_BYTES);
    cudaFuncSetAttribute(gemm_row<1>,          cudaFuncAttributeMaxDynamicSharedMemorySize, RSMEM_BYTES);

    static cudaStream_t s2 = nullptr;
    static cudaEvent_t evFork = nullptr, evJoin = nullptr;
    if (!s2) {
        cudaStreamCreateWithFlags(&s2, cudaStreamNonBlocking);
        cudaEventCreateWithFlags(&evFork, cudaEventDisableTiming);
        cudaEventCreateWithFlags(&evJoin, cudaEventDisableTiming);
    }

    const dim3 blk(256);
    const dim3 gB (4, 64);

    // fork: branch A (KV + memshift) on s2
    cudaEventRecord(evFork, 0);
    cudaStreamWaitEvent(s2, evFork, 0);
    gemm_dualB<<<dim3(4, 640), blk, SMEM2_BYTES, s2>>>(
        memflat, Wk, bk, kP, 256, Wv, bv, vP, 256, 256, 256);
    memshift_kernel<<<(B_ * 576 + 255) / 256, 256, 0, s2>>>(memflat, out + B_ * D_);
    cudaEventRecord(evJoin, s2);

    // branch B: z_t -> {xp, hp, new_entry} -> GRU
    gemm_single<0,false><<<gB, blk, SMEM_BYTES>>>(
        inputs, nullptr, W_in, b_in, zP, 256, 256, 256);
    {
        Batch3 p{};
        p.s[0] = { zP,     gru_k,  gru_b,       xpP, 768, 256, 768, 12 };
        p.s[1] = { h_prev, gru_rk, gru_b + 768, hpP, 768, 256, 768, 12 };
        p.s[2] = { zP,     W_mem,  b_mem,
                   out + B_ * D_ + (M_ - 1) * D_, 256, 256, M_ * D_, 4 };
        gemm_batched<<<dim3(12, 64, 3), blk, SMEM_BYTES>>>(p);
    }
    gru_kernel<<<(B_ * 64 + 255) / 256, 256>>>(h_prev);

    // join: attention needs K/V
    cudaStreamWaitEvent(0, evJoin, 0);

    // q-attention + gate-part1 in one launch (both consume gru)
    qpair_kernel<<<dim3(4, 64, 2), blk, SMEM_BYTES>>>(
        gruP, Wq, bq, ctxhP, W_gate, b_gate, p1P);

    // Wo GEMM with fused LN -> ctx
    gemm_row<0><<<128, blk, RSMEM_BYTES>>>(
        ctxhP, Wo, bo, g_attn, beta_attn, nullptr, nullptr, nullptr, ctxP);

    // ctx_p = tanh(ctx @ W_ctx + b_ctx)
    gemm_single<1,false><<<gB, blk, SMEM_BYTES>>>(
        ctxP, nullptr, W_ctx, b_ctx, ctxpP, 256, 256, 256);

    // gate2 + blend + LN -> h_corr (W_gate rows 256..511 multiply ctxp)
    gemm_row<1><<<128, blk, RSMEM_BYTES>>>(
        ctxpP, W_gate + 256 * 256, b_gate, g_out, beta_out,
        p1P, gruP, ctxpP, out);
}

// round 16
// speedup vs baseline: 1.0422x; 1.0422x over previous
#include <cuda_runtime.h>
#include <math.h>
#include <stdint.h>

#define B_  8192
#define D_  256
#define M_  10
#define H_  4
#define DK_ 64

// ---------------- scratch (device globals; no allocation allowed) ----------
__device__ float g_z   [B_*D_];
__device__ float g_xp  [B_*3*D_];
__device__ float g_hp  [B_*3*D_];
__device__ float g_gru [B_*D_];
__device__ float g_k   [B_*M_*D_];
__device__ float g_v   [B_*M_*D_];
__device__ float g_ctxh[B_*D_];
__device__ float g_ctx [B_*D_];
__device__ float g_ctxp[B_*D_];
__device__ float g_alph[B_*D_];

__device__ __forceinline__ float sigf(float x) { return 1.0f / (1.0f + expf(-x)); }

__device__ __forceinline__ void mma_tf32(float acc[4], const uint32_t a[4],
                                         uint32_t b0, uint32_t b1) {
    asm volatile(
        "mma.sync.aligned.m16n8k8.row.col.f32.tf32.tf32.f32 "
        "{%0,%1,%2,%3}, {%4,%5,%6,%7}, {%8,%9}, {%0,%1,%2,%3};"
        : "+f"(acc[0]), "+f"(acc[1]), "+f"(acc[2]), "+f"(acc[3])
        : "r"(a[0]), "r"(a[1]), "r"(a[2]), "r"(a[3]), "r"(b0), "r"(b1));
}

__device__ __forceinline__ void cp16(uint32_t dst, const void* src) {
    asm volatile("cp.async.cg.shared.global [%0], [%1], 16;" :: "r"(dst), "l"(src));
}
__device__ __forceinline__ void cp_commit() {
    asm volatile("cp.async.commit_group;" ::: "memory");
}
template<int N>
__device__ __forceinline__ void cp_wait() {
    asm volatile("cp.async.wait_group %0;" :: "n"(N) : "memory");
}

// ---- smem geometry (words) ----
#define AS_STRIDE 36
#define ABUF_W    (128 * AS_STRIDE)          // 4608
#define BS_STRIDE 72
#define BBUF_W    (32 * BS_STRIDE)           // 2304
#define STAGE_W   (ABUF_W + BBUF_W)
#define SMEM_BYTES  (2 * STAGE_W * 4)        // 55296 (narrow 128x64)
#define SMEM2_BYTES ((2 * ABUF_W + 4 * BBUF_W) * 4)  // 73728 (dual-B)
// wide kernel (128x128)
#define WBSTR  136
#define WBBUF  (32 * WBSTR)                  // 4352
#define WSTAGE (ABUF_W + WBBUF)              // 8960
#define WSMEM_BYTES (2 * WSTAGE * 4)         // 71680

// ---------------- tf32 GEMM core (device, 128x64 narrow) --------------------
// EPI: 0=identity, 3=fused attention epilogue.
template<int EPI, bool DUAL>
__device__ __forceinline__
void gemm_core(const float* __restrict__ A, const float* __restrict__ A2,
               const float* __restrict__ W, const float* __restrict__ bias,
               float* __restrict__ C, int N, int K, int ldc)
{
    extern __shared__ uint32_t sm[];
    const uint32_t sbase = (uint32_t)__cvta_generic_to_shared(sm);

    const int bm   = blockIdx.y * 128;
    const int bn   = blockIdx.x * 64;
    const int tid  = threadIdx.x;
    const int lane = tid & 31;
    const int wid  = tid >> 5;
    const int wm   = (wid & 3) * 32;
    const int wn   = (wid >> 2) * 32;
    const int g    = lane >> 2;
    const int q    = lane & 3;

    const int mi = lane >> 3, rr = lane & 7;
    const uint32_t a_off0 = ((wm + (mi & 1) * 8 + rr) * AS_STRIDE + (mi >> 1) * 4) * 4;
    const uint32_t a_off1 = a_off0 + 16 * AS_STRIDE * 4;
    const uint32_t b_off  = (q * BS_STRIDE + wn + g) * 4;

    float acc[2][4][4];
    #pragma unroll
    for (int t = 0; t < 2; t++)
        #pragma unroll
        for (int j = 0; j < 4; j++)
            #pragma unroll
            for (int e = 0; e < 4; e++) acc[t][j][e] = 0.0f;

    auto cp_tile = [&](int k0, int stage) {
        uint32_t abase = sbase + stage * (STAGE_W * 4);
        uint32_t bbase = abase + ABUF_W * 4;
        #pragma unroll
        for (int i = 0; i < 4; i++) {
            int idx = tid + i * 256;
            int row = idx >> 3, c4 = (idx & 7) * 4;
            int gk  = k0 + c4;
            const float* src;
            if (DUAL) {
                src = (gk < 256) ? &A [(size_t)(bm + row) * 256 + gk]
                                 : &A2[(size_t)(bm + row) * 256 + gk - 256];
            } else {
                src = &A[(size_t)(bm + row) * K + gk];
            }
            cp16(abase + (row * AS_STRIDE + c4) * 4, src);
        }
        #pragma unroll
        for (int i = 0; i < 2; i++) {
            int idx = tid + i * 256;
            int kk = idx >> 4, n0 = (idx & 15) * 4;
            cp16(bbase + (kk * BS_STRIDE + n0) * 4, &W[(size_t)(k0 + kk) * N + bn + n0]);
        }
    };

    auto load_frag = [&](uint32_t asb, uint32_t bsb, int kb,
                         uint32_t a0[4], uint32_t a1[4], uint32_t b0[4], uint32_t b1[4]) {
        asm volatile("ldmatrix.sync.aligned.m8n8.x4.shared.b16 {%0,%1,%2,%3}, [%4];"
            : "=r"(a0[0]), "=r"(a0[1]), "=r"(a0[2]), "=r"(a0[3]) : "r"(asb + a_off0 + kb * 32));
        asm volatile("ldmatrix.sync.aligned.m8n8.x4.shared.b16 {%0,%1,%2,%3}, [%4];"
            : "=r"(a1[0]), "=r"(a1[1]), "=r"(a1[2]), "=r"(a1[3]) : "r"(asb + a_off1 + kb * 32));
        uint32_t bb = bsb + b_off + kb * (8 * BS_STRIDE * 4);
        #pragma unroll
        for (int j = 0; j < 4; j++) {
            asm volatile("ld.shared.b32 %0, [%1];" : "=r"(b0[j]) : "r"(bb + j * 32));
            asm volatile("ld.shared.b32 %0, [%1];" : "=r"(b1[j]) : "r"(bb + j * 32 + 4 * BS_STRIDE * 4));
        }
    };

    auto compute = [&](int stage) {
        const uint32_t asb = sbase + stage * (STAGE_W * 4);
        const uint32_t bsb = asb + ABUF_W * 4;
        uint32_t a0[2][4], a1[2][4], b0[2][4], b1[2][4];
        load_frag(asb, bsb, 0, a0[0], a1[0], b0[0], b1[0]);
        #pragma unroll
        for (int kb = 0; kb < 4; kb++) {
            int cur = kb & 1, nxt = cur ^ 1;
            if (kb < 3) load_frag(asb, bsb, kb + 1, a0[nxt], a1[nxt], b0[nxt], b1[nxt]);
            #pragma unroll
            for (int j = 0; j < 4; j++) {
                mma_tf32(acc[0][j], a0[cur], b0[cur][j], b1[cur][j]);
                mma_tf32(acc[1][j], a1[cur], b0[cur][j], b1[cur][j]);
            }
        }
    };

    const int NIT = K >> 5;
    cp_tile(0, 0);
    cp_commit();
    for (int it = 0; it < NIT; it++) {
        cp_wait<0>();
        __syncthreads();
        if (it + 1 < NIT) {
            cp_tile((it + 1) * 32, (it + 1) & 1);
            cp_commit();
        }
        compute(it & 1);
    }

    if (EPI == 3) {
        float* qs = (float*)sm;            // 128 x 68 staging
        __syncthreads();
        #pragma unroll
        for (int t = 0; t < 2; t++) {
            #pragma unroll
            for (int j = 0; j < 4; j++) {
                int colL = wn + j * 8 + 2 * q;
                float b0v = bias[bn + colL], b1v = bias[bn + colL + 1];
                #pragma unroll
                for (int h2 = 0; h2 < 2; h2++) {
                    int rowL = wm + t * 16 + g + h2 * 8;
                    qs[rowL * 68 + colL]     = acc[t][j][2 * h2]     + b0v;
                    qs[rowL * 68 + colL + 1] = acc[t][j][2 * h2 + 1] + b1v;
                }
            }
        }
        __syncthreads();
        const int head = blockIdx.x;       // bn = 64*head
        for (int r2 = 0; r2 < 16; r2++) {
            int row = wid * 16 + r2;
            size_t b = bm + row;
            float2 qv = *(float2*)&qs[row * 68 + 2 * lane];
            float sc[M_];
            #pragma unroll
            for (int m = 0; m < M_; m++) {
                const float* kp = g_k + (b * M_ + m) * D_ + head * DK_;
                float p = qv.x * kp[2 * lane] + qv.y * kp[2 * lane + 1];
                #pragma unroll
                for (int o = 16; o > 0; o >>= 1) p += __shfl_xor_sync(0xffffffffu, p, o);
                sc[m] = p * 0.125f;
            }
            float mx = sc[0];
            #pragma unroll
            for (int m = 1; m < M_; m++) mx = fmaxf(mx, sc[m]);
            float sum = 0.0f;
            #pragma unroll
            for (int m = 0; m < M_; m++) { sc[m] = expf(sc[m] - mx); sum += sc[m]; }
            float inv = 1.0f / sum;
            float c0 = 0.0f, c1 = 0.0f;
            #pragma unroll
            for (int m = 0; m < M_; m++) {
                const float* vp = g_v + (b * M_ + m) * D_ + head * DK_;
                float a = sc[m] * inv;
                c0 += a * vp[2 * lane];
                c1 += a * vp[2 * lane + 1];
            }
            *(float2*)&C[b * ldc + bn + 2 * lane] = make_float2(c0, c1);
        }
        return;
    }

    #pragma unroll
    for (int t = 0; t < 2; t++) {
        #pragma unroll
        for (int j = 0; j < 4; j++) {
            int col = bn + wn + j * 8 + 2 * q;
            float b0 = bias[col], b1 = bias[col + 1];
            #pragma unroll
            for (int h = 0; h < 2; h++) {
                int row = bm + wm + t * 16 + g + h * 8;
                *(float2*)&C[(size_t)row * ldc + col] =
                    make_float2(acc[t][j][2 * h] + b0, acc[t][j][2 * h + 1] + b1);
            }
        }
    }
}

template<int EPI, bool DUAL>
__global__ __launch_bounds__(256, 4)
void gemm_single(const float* __restrict__ A, const float* __restrict__ A2,
                 const float* __restrict__ W, const float* __restrict__ bias,
                 float* __restrict__ C, int N, int K, int ldc)
{
    gemm_core<EPI, DUAL>(A, A2, W, bias, C, N, K, ldc);
}

// ---------------- WIDE tf32 GEMM core (128x128, warp tile 32x64) ------------
// Arithmetic intensity: A read 2x + B read 4x = 96KB smem per 512 tensor-cyc
// (1.5:1) vs narrow 2:1. EPI: 0=identity, 1=tanh, 2=sigmoid.
template<int EPI, bool DUAL>
__device__ __forceinline__
void gemm_wide_core(const float* __restrict__ A, const float* __restrict__ A2,
                    const float* __restrict__ W, const float* __restrict__ bias,
                    float* __restrict__ C, int N, int K, int ldc)
{
    extern __shared__ uint32_t sm[];
    const uint32_t sbase = (uint32_t)__cvta_generic_to_shared(sm);

    const int bm   = blockIdx.y * 128;
    const int bn   = blockIdx.x * 128;
    const int tid  = threadIdx.x;
    const int lane = tid & 31;
    const int wid  = tid >> 5;
    const int wm   = (wid & 3) * 32;
    const int wn   = (wid >> 2) * 64;
    const int g    = lane >> 2;
    const int q    = lane & 3;

    const int mi = lane >> 3, rr = lane & 7;
    const uint32_t a_off0 = ((wm + (mi & 1) * 8 + rr) * AS_STRIDE + (mi >> 1) * 4) * 4;
    const uint32_t a_off1 = a_off0 + 16 * AS_STRIDE * 4;
    // scalar B frag: addr = q*WBSTR + wn + 8j + g; banks (8q+g+c) all distinct
    const uint32_t b_off  = (q * WBSTR + wn + g) * 4;

    float acc[2][8][4];
    #pragma unroll
    for (int t = 0; t < 2; t++)
        #pragma unroll
        for (int j = 0; j < 8; j++)
            #pragma unroll
            for (int e = 0; e < 4; e++) acc[t][j][e] = 0.0f;

    auto cp_tile = [&](int k0, int stage) {
        uint32_t abase = sbase + stage * (WSTAGE * 4);
        uint32_t bbase = abase + ABUF_W * 4;
        #pragma unroll
        for (int i = 0; i < 4; i++) {
            int idx = tid + i * 256;
            int row = idx >> 3, c4 = (idx & 7) * 4;
            int gk  = k0 + c4;
            const float* src;
            if (DUAL) {
                src = (gk < 256) ? &A [(size_t)(bm + row) * 256 + gk]
                                 : &A2[(size_t)(bm + row) * 256 + gk - 256];
            } else {
                src = &A[(size_t)(bm + row) * K + gk];
            }
            cp16(abase + (row * AS_STRIDE + c4) * 4, src);
        }
        #pragma unroll
        for (int i = 0; i < 4; i++) {
            int idx = tid + i * 256;
            int kk = idx >> 5, n0 = (idx & 31) * 4;
            cp16(bbase + (kk * WBSTR + n0) * 4, &W[(size_t)(k0 + kk) * N + bn + n0]);
        }
    };

    auto compute = [&](int stage) {
        const uint32_t asb = sbase + stage * (WSTAGE * 4);
        const uint32_t bsb = asb + ABUF_W * 4;
        #pragma unroll
        for (int kb = 0; kb < 4; kb++) {
            uint32_t a0[4], a1[4];
            asm volatile("ldmatrix.sync.aligned.m8n8.x4.shared.b16 {%0,%1,%2,%3}, [%4];"
                : "=r"(a0[0]), "=r"(a0[1]), "=r"(a0[2]), "=r"(a0[3])
                : "r"(asb + a_off0 + kb * 32));
            asm volatile("ldmatrix.sync.aligned.m8n8.x4.shared.b16 {%0,%1,%2,%3}, [%4];"
                : "=r"(a1[0]), "=r"(a1[1]), "=r"(a1[2]), "=r"(a1[3])
                : "r"(asb + a_off1 + kb * 32));
            uint32_t bb = bsb + b_off + kb * (8 * WBSTR * 4);
            #pragma unroll
            for (int j = 0; j < 8; j++) {
                uint32_t b0, b1;
                asm volatile("ld.shared.b32 %0, [%1];" : "=r"(b0) : "r"(bb + j * 32));
                asm volatile("ld.shared.b32 %0, [%1];" : "=r"(b1) : "r"(bb + j * 32 + 4 * WBSTR * 4));
                mma_tf32(acc[0][j], a0, b0, b1);
                mma_tf32(acc[1][j], a1, b0, b1);
            }
        }
    };

    const int NIT = K >> 5;
    cp_tile(0, 0);
    cp_commit();
    for (int it = 0; it < NIT; it++) {
        cp_wait<0>();
        __syncthreads();
        if (it + 1 < NIT) {
            cp_tile((it + 1) * 32, (it + 1) & 1);
            cp_commit();
        }
        compute(it & 1);
    }

    #pragma unroll
    for (int t = 0; t < 2; t++) {
        #pragma unroll
        for (int j = 0; j < 8; j++) {
            int col = bn + wn + j * 8 + 2 * q;
            float b0 = bias[col], b1 = bias[col + 1];
            #pragma unroll
            for (int h = 0; h < 2; h++) {
                int row = bm + wm + t * 16 + g + h * 8;
                float v0 = acc[t][j][2 * h]     + b0;
                float v1 = acc[t][j][2 * h + 1] + b1;
                if (EPI == 1) { v0 = tanhf(v0); v1 = tanhf(v1); }
                if (EPI == 2) { v0 = sigf(v0);  v1 = sigf(v1);  }
                *(float2*)&C[(size_t)row * ldc + col] = make_float2(v0, v1);
            }
        }
    }
}

template<int EPI, bool DUAL>
__global__ __launch_bounds__(256, 2)
void gemm_wide(const float* __restrict__ A, const float* __restrict__ A2,
               const float* __restrict__ W, const float* __restrict__ bias,
               float* __restrict__ C, int N, int K, int ldc)
{
    gemm_wide_core<EPI, DUAL>(A, A2, W, bias, C, N, K, ldc);
}

// z-batched wide wrapper (independent slices)
struct Slice {
    const float* A; const float* W; const float* bias; float* C;
    int N; int K; int ldc; int gx;
};
struct Batch3 { Slice s[3]; };

__global__ __launch_bounds__(256, 2)
void gemm_batched_w(Batch3 p)
{
    Slice sl = p.s[blockIdx.z];
    if ((int)blockIdx.x >= sl.gx) return;
    gemm_wide_core<0, false>(sl.A, nullptr, sl.W, sl.bias, sl.C, sl.N, sl.K, sl.ldc);
}

// ---------------- dual-B shared-A GEMM: C0 = A@W0+b0, C1 = A@W1+b1 ----------
__global__ __launch_bounds__(256, 2)
void gemm_dualB(const float* __restrict__ A,
                const float* __restrict__ W0, const float* __restrict__ bias0,
                float* __restrict__ C0, int ldc0,
                const float* __restrict__ W1, const float* __restrict__ bias1,
                float* __restrict__ C1, int ldc1,
                int N, int K)
{
    extern __shared__ uint32_t sm[];
    const uint32_t sbase = (uint32_t)__cvta_generic_to_shared(sm);

    const int bm   = blockIdx.y * 128;
    const int bn   = blockIdx.x * 64;
    const int tid  = threadIdx.x;
    const int lane = tid & 31;
    const int wid  = tid >> 5;
    const int wm   = (wid & 3) * 32;
    const int wn   = (wid >> 2) * 32;
    const int g    = lane >> 2;
    const int q    = lane & 3;

    const int mi = lane >> 3, rr = lane & 7;
    const uint32_t a_off0 = ((wm + (mi & 1) * 8 + rr) * AS_STRIDE + (mi >> 1) * 4) * 4;
    const uint32_t a_off1 = a_off0 + 16 * AS_STRIDE * 4;
    const uint32_t b_off  = (q * BS_STRIDE + wn + g) * 4;

    float acc[2][2][4][4];
    #pragma unroll
    for (int p = 0; p < 2; p++)
        #pragma unroll
        for (int t = 0; t < 2; t++)
            #pragma unroll
            for (int j = 0; j < 4; j++)
                #pragma unroll
                for (int e = 0; e < 4; e++) acc[p][t][j][e] = 0.0f;

    auto cp_tile = [&](int k0, int stage) {
        uint32_t abase  = sbase + stage * (ABUF_W * 4);
        uint32_t bbase0 = sbase + (2 * ABUF_W + (2 * stage + 0) * BBUF_W) * 4;
        uint32_t bbase1 = sbase + (2 * ABUF_W + (2 * stage + 1) * BBUF_W) * 4;
        #pragma unroll
        for (int i = 0; i < 4; i++) {
            int idx = tid + i * 256;
            int row = idx >> 3, c4 = (idx & 7) * 4;
            cp16(abase + (row * AS_STRIDE + c4) * 4, &A[(size_t)(bm + row) * K + k0 + c4]);
        }
        #pragma unroll
        for (int i = 0; i < 2; i++) {
            int idx = tid + i * 256;
            int kk = idx >> 4, n0 = (idx & 15) * 4;
            cp16(bbase0 + (kk * BS_STRIDE + n0) * 4, &W0[(size_t)(k0 + kk) * N + bn + n0]);
            cp16(bbase1 + (kk * BS_STRIDE + n0) * 4, &W1[(size_t)(k0 + kk) * N + bn + n0]);
        }
    };

    auto compute = [&](int stage) {
        const uint32_t asb = sbase + stage * (ABUF_W * 4);
        #pragma unroll
        for (int kb = 0; kb < 4; kb++) {
            uint32_t a0[4], a1[4];
            asm volatile("ldmatrix.sync.aligned.m8n8.x4.shared.b16 {%0,%1,%2,%3}, [%4];"
                : "=r"(a0[0]), "=r"(a0[1]), "=r"(a0[2]), "=r"(a0[3])
                : "r"(asb + a_off0 + kb * 32));
            asm volatile("ldmatrix.sync.aligned.m8n8.x4.shared.b16 {%0,%1,%2,%3}, [%4];"
                : "=r"(a1[0]), "=r"(a1[1]), "=r"(a1[2]), "=r"(a1[3])
                : "r"(asb + a_off1 + kb * 32));
            #pragma unroll
            for (int p = 0; p < 2; p++) {
                uint32_t bsb = sbase + (2 * ABUF_W + (2 * stage + p) * BBUF_W) * 4;
                uint32_t bb  = bsb + b_off + kb * (8 * BS_STRIDE * 4);
                uint32_t b0[4], b1[4];
                #pragma unroll
                for (int j = 0; j < 4; j++) {
                    asm volatile("ld.shared.b32 %0, [%1];" : "=r"(b0[j]) : "r"(bb + j * 32));
                    asm volatile("ld.shared.b32 %0, [%1];" : "=r"(b1[j]) : "r"(bb + j * 32 + 4 * BS_STRIDE * 4));
                }
                #pragma unroll
                for (int j = 0; j < 4; j++) {
                    mma_tf32(acc[p][0][j], a0, b0[j], b1[j]);
                    mma_tf32(acc[p][1][j], a1, b0[j], b1[j]);
                }
            }
        }
    };

    const int NIT = K >> 5;
    cp_tile(0, 0);
    cp_commit();
    for (int it = 0; it < NIT; it++) {
        cp_wait<0>();
        __syncthreads();
        if (it + 1 < NIT) {
            cp_tile((it + 1) * 32, (it + 1) & 1);
            cp_commit();
        }
        compute(it & 1);
    }

    #pragma unroll
    for (int p = 0; p < 2; p++) {
        const float* bias = p ? bias1 : bias0;
        float*       C    = p ? C1    : C0;
        int          ldc  = p ? ldc1  : ldc0;
        #pragma unroll
        for (int t = 0; t < 2; t++) {
            #pragma unroll
            for (int j = 0; j < 4; j++) {
                int col = bn + wn + j * 8 + 2 * q;
                float b0 = bias[col], b1 = bias[col + 1];
                #pragma unroll
                for (int h = 0; h < 2; h++) {
                    int row = bm + wm + t * 16 + g + h * 8;
                    *(float2*)&C[(size_t)row * ldc + col] =
                        make_float2(acc[p][t][j][2 * h] + b0, acc[p][t][j][2 * h + 1] + b1);
                }
            }
        }
    }
}

// ---------------- GRU elementwise, float4 vectorized ------------------------
__global__ void gru_kernel(const float* __restrict__ h_prev)
{
    int idx = blockIdx.x * blockDim.x + threadIdx.x;
    if (idx >= B_ * 64) return;
    int b = idx >> 6, d4 = (idx & 63) * 4;
    const float* xp = g_xp + (size_t)b * 768;
    const float* hp = g_hp + (size_t)b * 768;
    float4 xz = *(const float4*)(xp + d4);
    float4 xr = *(const float4*)(xp + 256 + d4);
    float4 xh = *(const float4*)(xp + 512 + d4);
    float4 hz = *(const float4*)(hp + d4);
    float4 hr = *(const float4*)(hp + 256 + d4);
    float4 hh = *(const float4*)(hp + 512 + d4);
    float4 h  = *(const float4*)(h_prev + (size_t)b * 256 + d4);
    float4 o;
    { float z = sigf(xz.x + hz.x), r = sigf(xr.x + hr.x);
      float hc = tanhf(xh.x + r * hh.x); o.x = z * h.x + (1.0f - z) * hc; }
    { float z = sigf(xz.y + hz.y), r = sigf(xr.y + hr.y);
      float hc = tanhf(xh.y + r * hh.y); o.y = z * h.y + (1.0f - z) * hc; }
    { float z = sigf(xz.z + hz.z), r = sigf(xr.z + hr.z);
      float hc = tanhf(xh.z + r * hh.z); o.z = z * h.z + (1.0f - z) * hc; }
    { float z = sigf(xz.w + hz.w), r = sigf(xr.w + hr.w);
      float hc = tanhf(xh.w + r * hh.w); o.w = z * h.w + (1.0f - z) * hc; }
    *(float4*)(g_gru + (size_t)b * 256 + d4) = o;
}

// ---------------- LayerNorm (warp per row, D = 256) -------------------------
__device__ __forceinline__ void ln_row(const float* x8, int lane,
                                       const float* __restrict__ gm,
                                       const float* __restrict__ bt,
                                       float* __restrict__ yrow)
{
    float s = 0.0f, ss = 0.0f;
    #pragma unroll
    for (int i = 0; i < 8; i++) { s += x8[i]; ss += x8[i] * x8[i]; }
    #pragma unroll
    for (int o = 16; o > 0; o >>= 1) {
        s  += __shfl_xor_sync(0xffffffffu, s,  o);
        ss += __shfl_xor_sync(0xffffffffu, ss, o);
    }
    float mu  = s * (1.0f / 256.0f);
    float var = ss * (1.0f / 256.0f) - mu * mu;
    float inv = rsqrtf(var + 1e-3f);
    float out[8];
    #pragma unroll
    for (int i = 0; i < 8; i++) {
        int d = lane * 8 + i;
        out[i] = (x8[i] - mu) * inv * gm[d] + bt[d];
    }
    *(float4*)(yrow + lane * 8)     = make_float4(out[0], out[1], out[2], out[3]);
    *(float4*)(yrow + lane * 8 + 4) = make_float4(out[4], out[5], out[6], out[7]);
}

__global__ void ln_kernel(const float* __restrict__ x, const float* __restrict__ gm,
                          const float* __restrict__ bt, float* __restrict__ y)
{
    int w    = (blockIdx.x * blockDim.x + threadIdx.x) >> 5;
    int lane = threadIdx.x & 31;
    if (w >= B_) return;
    const float* row = x + (size_t)w * D_;
    float4 v0 = *(const float4*)(row + lane * 8);
    float4 v1 = *(const float4*)(row + lane * 8 + 4);
    float x8[8] = {v0.x, v0.y, v0.z, v0.w, v1.x, v1.y, v1.z, v1.w};
    ln_row(x8, lane, gm, bt, y + (size_t)w * D_);
}

__global__ void blend_ln_kernel(const float* __restrict__ gm,
                                const float* __restrict__ bt,
                                float* __restrict__ out)
{
    int w    = (blockIdx.x * blockDim.x + threadIdx.x) >> 5;
    int lane = threadIdx.x & 31;
    if (w >= B_) return;
    size_t base = (size_t)w * D_ + lane * 8;
    float x8[8];
    #pragma unroll
    for (int i = 0; i < 8; i++) {
        float a = g_alph[base + i];
        x8[i] = (1.0f - a) * g_gru[base + i] + a * g_ctxp[base + i];
    }
    ln_row(x8, lane, gm, bt, out + (size_t)w * D_);
}

// ---------------- memory shift ---------------------------------------------
__global__ void memshift_kernel(const float* __restrict__ memflat,
                                float* __restrict__ outmem)
{
    const int per = (M_ - 1) * D_ / 4;
    int idx = blockIdx.x * blockDim.x + threadIdx.x;
    if (idx >= B_ * per) return;
    int b = idx / per, j = idx - b * per;
    const float4* src = (const float4*)(memflat + (size_t)b * (M_ * D_) + D_);
    float4*       dst = (float4*)(outmem + (size_t)b * (M_ * D_));
    dst[j] = src[j];
}

// ---------------- host ------------------------------------------------------
extern "C" void kernel_launch(void* const* d_in, const int* in_sizes, int n_in,
                              void* d_out, int out_size)
{
    const float* inputs    = (const float*)d_in[0];
    const float* h_prev    = (const float*)d_in[1];
    const float* memflat   = (const float*)d_in[2];
    const float* W_in      = (const float*)d_in[3];
    const float* b_in      = (const float*)d_in[4];
    const float* gru_k     = (const float*)d_in[5];
    const float* gru_rk    = (const float*)d_in[6];
    const float* gru_b     = (const float*)d_in[7];
    const float* Wq        = (const float*)d_in[8];
    const float* bq        = (const float*)d_in[9];
    const float* Wk        = (const float*)d_in[10];
    const float* bk        = (const float*)d_in[11];
    const float* Wv        = (const float*)d_in[12];
    const float* bv        = (const float*)d_in[13];
    const float* Wo        = (const float*)d_in[14];
    const float* bo        = (const float*)d_in[15];
    const float* g_attn    = (const float*)d_in[16];
    const float* beta_attn = (const float*)d_in[17];
    const float* g_out     = (const float*)d_in[18];
    const float* beta_out  = (const float*)d_in[19];
    const float* W_ctx     = (const float*)d_in[20];
    const float* b_ctx     = (const float*)d_in[21];
    const float* W_gate    = (const float*)d_in[22];
    const float* b_gate    = (const float*)d_in[23];
    const float* W_mem     = (const float*)d_in[24];
    const float* b_mem     = (const float*)d_in[25];
    float* out = (float*)d_out;

    float *zP, *xpP, *hpP, *gruP, *kP, *vP, *ctxhP, *ctxP, *ctxpP, *alphP;
    cudaGetSymbolAddress((void**)&zP,    g_z);
    cudaGetSymbolAddress((void**)&xpP,   g_xp);
    cudaGetSymbolAddress((void**)&hpP,   g_hp);
    cudaGetSymbolAddress((void**)&gruP,  g_gru);
    cudaGetSymbolAddress((void**)&kP,    g_k);
    cudaGetSymbolAddress((void**)&vP,    g_v);
    cudaGetSymbolAddress((void**)&ctxhP, g_ctxh);
    cudaGetSymbolAddress((void**)&ctxP,  g_ctx);
    cudaGetSymbolAddress((void**)&ctxpP, g_ctxp);
    cudaGetSymbolAddress((void**)&alphP, g_alph);

    cudaFuncSetAttribute(gemm_single<3,false>, cudaFuncAttributeMaxDynamicSharedMemorySize, SMEM_BYTES);
    cudaFuncSetAttribute(gemm_wide<0,false>,   cudaFuncAttributeMaxDynamicSharedMemorySize, WSMEM_BYTES);
    cudaFuncSetAttribute(gemm_wide<1,false>,   cudaFuncAttributeMaxDynamicSharedMemorySize, WSMEM_BYTES);
    cudaFuncSetAttribute(gemm_wide<2,true >,   cudaFuncAttributeMaxDynamicSharedMemorySize, WSMEM_BYTES);
    cudaFuncSetAttribute(gemm_batched_w,       cudaFuncAttributeMaxDynamicSharedMemorySize, WSMEM_BYTES);
    cudaFuncSetAttribute(gemm_dualB,           cudaFuncAttributeMaxDynamicSharedMemorySize, SMEM2_BYTES);

    static cudaStream_t s2 = nullptr;
    static cudaEvent_t evFork = nullptr, evJoin = nullptr;
    if (!s2) {
        cudaStreamCreateWithFlags(&s2, cudaStreamNonBlocking);
        cudaEventCreateWithFlags(&evFork, cudaEventDisableTiming);
        cudaEventCreateWithFlags(&evJoin, cudaEventDisableTiming);
    }

    const dim3 blk(256);
    const dim3 gW (2, 64);     // wide: 8192 x 256

    // fork: branch A (KV + memshift) on s2
    cudaEventRecord(evFork, 0);
    cudaStreamWaitEvent(s2, evFork, 0);
    gemm_dualB<<<dim3(4, 640), blk, SMEM2_BYTES, s2>>>(
        memflat, Wk, bk, kP, 256, Wv, bv, vP, 256, 256, 256);
    memshift_kernel<<<(B_ * 576 + 255) / 256, 256, 0, s2>>>(memflat, out + B_ * D_);
    cudaEventRecord(evJoin, s2);

    // branch B: z_t -> {xp, hp, new_entry} -> GRU
    gemm_wide<0,false><<<gW, blk, WSMEM_BYTES>>>(
        inputs, nullptr, W_in, b_in, zP, 256, 256, 256);
    {
        Batch3 p{};
        p.s[0] = { zP,     gru_k,  gru_b,       xpP, 768, 256, 768, 6 };
        p.s[1] = { h_prev, gru_rk, gru_b + 768, hpP, 768, 256, 768, 6 };
        p.s[2] = { zP,     W_mem,  b_mem,
                   out + B_ * D_ + (M_ - 1) * D_, 256, 256, M_ * D_, 2 };
        gemm_batched_w<<<dim3(6, 64, 3), blk, WSMEM_BYTES>>>(p);
    }
    gru_kernel<<<(B_ * 64 + 255) / 256, 256>>>(h_prev);

    // join: attention needs K/V
    cudaStreamWaitEvent(0, evJoin, 0);

    // q-GEMM with fused attention epilogue -> ctx_h (narrow: BN=64 per head)
    gemm_single<3,false><<<dim3(4, 64), blk, SMEM_BYTES>>>(
        gruP, nullptr, Wq, bq, ctxhP, 256, 256, 256);

    gemm_wide<0,false><<<gW, blk, WSMEM_BYTES>>>(ctxhP, nullptr, Wo, bo, ctxP, 256, 256, 256);
    ln_kernel<<<(B_ * 32 + 255) / 256, 256>>>(ctxP, g_attn, beta_attn, ctxP);

    gemm_wide<1,false><<<gW, blk, WSMEM_BYTES>>>(ctxP, nullptr, W_ctx, b_ctx, ctxpP, 256, 256, 256);
    gemm_wide<2,true ><<<gW, blk, WSMEM_BYTES>>>(gruP, ctxpP, W_gate, b_gate, alphP, 256, 512, 256);
    blend_ln_kernel<<<(B_ * 32 + 255) / 256, 256>>>(g_out, beta_out, out);
}